// round 6
// baseline (speedup 1.0000x reference)
#include <cuda_runtime.h>
#include <cuda_fp16.h>
#include <cstdint>

#define B 8
#define TE 512
#define TD 256
#define H 256

typedef unsigned long long ull;
typedef unsigned int uint;

// Scratch (device globals: no allocations allowed)
__device__ float g_WeT[B * H * TE];  // [b][h][i]
__device__ float g_Uh [B * TD * H];  // [b][j][h]

// ---- packed fp32x2 helpers ----
__device__ __forceinline__ ull pk2(float lo, float hi) {
    ull r; asm("mov.b64 %0, {%1, %2};" : "=l"(r) : "f"(lo), "f"(hi)); return r;
}
__device__ __forceinline__ ull fma2(ull a, ull b, ull c) {
    ull d; asm("fma.rn.f32x2 %0, %1, %2, %3;" : "=l"(d) : "l"(a), "l"(b), "l"(c)); return d;
}
__device__ __forceinline__ void upk2(ull v, float& lo, float& hi) {
    asm("mov.b64 {%0, %1}, %2;" : "=f"(lo), "=f"(hi) : "l"(v));
}

// half2 tanh via MUFU (2 tanh per MUFU slot)
__device__ __forceinline__ uint tanh_h2(uint x) {
    uint y;
    asm("tanh.approx.f16x2 %0, %1;" : "=r"(y) : "r"(x));
    return y;
}

// 4x4 micro-tile step, rows packed in pairs, cols duplicated
__device__ __forceinline__ void micro_fma2(ull acc2[2][4], float4 a, float4 bb) {
    ull pa0 = pk2(a.x, a.y);
    ull pa1 = pk2(a.z, a.w);
    ull pb0 = pk2(bb.x, bb.x);
    ull pb1 = pk2(bb.y, bb.y);
    ull pb2 = pk2(bb.z, bb.z);
    ull pb3 = pk2(bb.w, bb.w);
    acc2[0][0] = fma2(pa0, pb0, acc2[0][0]);
    acc2[0][1] = fma2(pa0, pb1, acc2[0][1]);
    acc2[0][2] = fma2(pa0, pb2, acc2[0][2]);
    acc2[0][3] = fma2(pa0, pb3, acc2[0][3]);
    acc2[1][0] = fma2(pa1, pb0, acc2[1][0]);
    acc2[1][1] = fma2(pa1, pb1, acc2[1][1]);
    acc2[1][2] = fma2(pa1, pb2, acc2[1][2]);
    acc2[1][3] = fma2(pa1, pb3, acc2[1][3]);
}

// ---------------------------------------------------------------------------
// Fused GEMM, double-buffered (unchanged from R5 passing version).
// blockIdx.x < 8  -> WeT:  g_WeT[b][h][i] = enc[b][i][:] . W[:][h]
// blockIdx.x >= 8 -> Uh :  g_Uh[b][j][h]  = dec[b][j][:] . U[:][h]
// ---------------------------------------------------------------------------
__global__ __launch_bounds__(256) void gemm_fused(const float* __restrict__ enc,
                                                  const float* __restrict__ dec,
                                                  const float* __restrict__ W,
                                                  const float* __restrict__ U) {
    __shared__ float As[2][16][64];
    __shared__ float Bs[2][16][68];

    int b = blockIdx.z;
    int t = threadIdx.x;
    int tx = t & 15;
    int ty = t >> 4;

    ull acc2[2][4];
#pragma unroll
    for (int rp = 0; rp < 2; rp++)
#pragma unroll
        for (int c = 0; c < 4; c++) acc2[rp][c] = 0ull;

    bool weT = (blockIdx.x < 8);
    const float* Wm  = weT ? W : U;
    const float* act = weT ? (enc + (size_t)b * TE * H) : (dec + (size_t)b * TD * H);
    int h0 = blockIdx.y * 64;
    int c0 = weT ? blockIdx.x * 64 : (blockIdx.x - 8) * 64;

    int ka = t >> 4, hq = t & 15;
    int cc = t >> 2, kq = t & 3;

    {
        float4 aReg = *(const float4*)&Wm[ka * H + h0 + hq * 4];
        float4 bReg = *(const float4*)&act[(c0 + cc) * H + kq * 4];
        *(float4*)&As[0][ka][hq * 4] = aReg;
        Bs[0][kq * 4 + 0][cc] = bReg.x;
        Bs[0][kq * 4 + 1][cc] = bReg.y;
        Bs[0][kq * 4 + 2][cc] = bReg.z;
        Bs[0][kq * 4 + 3][cc] = bReg.w;
    }
    __syncthreads();

    if (weT) {
#pragma unroll 1
        for (int kt = 0; kt < 16; kt++) {
            int cur = kt & 1;
            float4 aReg, bReg;
            if (kt < 15) {
                int k0 = (kt + 1) * 16;
                aReg = *(const float4*)&Wm[(k0 + ka) * H + h0 + hq * 4];
                bReg = *(const float4*)&act[(c0 + cc) * H + k0 + kq * 4];
            }
#pragma unroll
            for (int kk = 0; kk < 16; kk++) {
                float4 a  = *(float4*)&As[cur][kk][ty * 4];
                float4 bb = *(float4*)&Bs[cur][kk][tx * 4];
                micro_fma2(acc2, a, bb);
            }
            if (kt < 15) {
                int nxt = cur ^ 1;
                *(float4*)&As[nxt][ka][hq * 4] = aReg;
                Bs[nxt][kq * 4 + 0][cc] = bReg.x;
                Bs[nxt][kq * 4 + 1][cc] = bReg.y;
                Bs[nxt][kq * 4 + 2][cc] = bReg.z;
                Bs[nxt][kq * 4 + 3][cc] = bReg.w;
                __syncthreads();
            }
        }
        float o[4][4];
#pragma unroll
        for (int rp = 0; rp < 2; rp++)
#pragma unroll
            for (int c = 0; c < 4; c++)
                upk2(acc2[rp][c], o[2 * rp][c], o[2 * rp + 1][c]);
        float* out = g_WeT + (size_t)b * H * TE;
#pragma unroll
        for (int r = 0; r < 4; r++) {
            float4 v = make_float4(o[r][0], o[r][1], o[r][2], o[r][3]);
            *(float4*)&out[(h0 + ty * 4 + r) * TE + c0 + tx * 4] = v;
        }
    } else {
#pragma unroll 1
        for (int kt = 0; kt < 16; kt++) {
            int cur = kt & 1;
            float4 aReg, bReg;
            if (kt < 15) {
                int k0 = (kt + 1) * 16;
                aReg = *(const float4*)&Wm[(k0 + ka) * H + h0 + hq * 4];
                bReg = *(const float4*)&act[(c0 + cc) * H + k0 + kq * 4];
            }
#pragma unroll
            for (int kk = 0; kk < 16; kk++) {
                float4 a  = *(float4*)&Bs[cur][kk][ty * 4];
                float4 bb = *(float4*)&As[cur][kk][tx * 4];
                micro_fma2(acc2, a, bb);
            }
            if (kt < 15) {
                int nxt = cur ^ 1;
                *(float4*)&As[nxt][ka][hq * 4] = aReg;
                Bs[nxt][kq * 4 + 0][cc] = bReg.x;
                Bs[nxt][kq * 4 + 1][cc] = bReg.y;
                Bs[nxt][kq * 4 + 2][cc] = bReg.z;
                Bs[nxt][kq * 4 + 3][cc] = bReg.w;
                __syncthreads();
            }
        }
        float o[4][4];
#pragma unroll
        for (int rp = 0; rp < 2; rp++)
#pragma unroll
            for (int c = 0; c < 4; c++)
                upk2(acc2[rp][c], o[2 * rp][c], o[2 * rp + 1][c]);
        float* out = g_Uh + (size_t)b * TD * H;
#pragma unroll
        for (int r = 0; r < 4; r++) {
            float4 v = make_float4(o[r][0], o[r][1], o[r][2], o[r][3]);
            *(float4*)&out[(c0 + ty * 4 + r) * H + h0 + tx * 4] = v;
        }
    }
}

// ---------------------------------------------------------------------------
// Energy + softmax with f16x2 MUFU tanh (2 tanh per MUFU slot).
// JT=4: one block per (b, 4 decoder rows) -> 512 blocks, 512 threads.
// x = w+u computed fp32, rounded to half2, tanh'd in pairs, accumulated fp32.
// ---------------------------------------------------------------------------
__global__ __launch_bounds__(512) void energy_kernel(const float* __restrict__ Va,
                                                     float* __restrict__ e_out) {
    __shared__ float Us4[H * 4];     // [h][jj]
    __shared__ float Vs[H];
    __shared__ float red[16][4];
    __shared__ float binv[4];

    int t  = threadIdx.x;
    int b  = blockIdx.x >> 6;            // TD/4 = 64 tiles per batch
    int j0 = (blockIdx.x & 63) * 4;

    for (int idx = t; idx < 4 * H; idx += 512) {
        int jj = idx >> 8;               // 0..3
        int h  = idx & (H - 1);
        Us4[h * 4 + jj] = g_Uh[((size_t)b * TD + j0 + jj) * H + h];
    }
    if (t < H) Vs[t] = Va[t];
    __syncthreads();

    const int i = t;
    const float* wp = g_WeT + (size_t)b * H * TE + i;

    float acc0 = 0.f, acc1 = 0.f, acc2 = 0.f, acc3 = 0.f;
#pragma unroll 4
    for (int h = 0; h < H; h++) {
        float w = wp[h * TE];
        float4 u = *(const float4*)&Us4[h * 4];
        float v = Vs[h];
        __half2 xa = __floats2half2_rn(w + u.x, w + u.y);
        __half2 xb = __floats2half2_rn(w + u.z, w + u.w);
        uint ya = tanh_h2(*(uint*)&xa);
        uint yb = tanh_h2(*(uint*)&xb);
        float2 ta = __half22float2(*(__half2*)&ya);
        float2 tb = __half22float2(*(__half2*)&yb);
        acc0 = fmaf(v, ta.x, acc0);
        acc1 = fmaf(v, ta.y, acc1);
        acc2 = fmaf(v, tb.x, acc2);
        acc3 = fmaf(v, tb.y, acc3);
    }

    // ---- softmax over i (no max subtraction; |energy| <= sum|V| <= ~13) ----
    float p0 = __expf(acc0);
    float p1 = __expf(acc1);
    float p2 = __expf(acc2);
    float p3 = __expf(acc3);

    int lane = t & 31, wrp = t >> 5;
    float s0 = p0, s1 = p1, s2 = p2, s3 = p3;
#pragma unroll
    for (int o = 16; o; o >>= 1) {
        s0 += __shfl_xor_sync(0xffffffffu, s0, o);
        s1 += __shfl_xor_sync(0xffffffffu, s1, o);
        s2 += __shfl_xor_sync(0xffffffffu, s2, o);
        s3 += __shfl_xor_sync(0xffffffffu, s3, o);
    }
    if (lane == 0) { red[wrp][0] = s0; red[wrp][1] = s1; red[wrp][2] = s2; red[wrp][3] = s3; }
    __syncthreads();
    if (t < 4) {
        float s = 0.f;
#pragma unroll
        for (int w2 = 0; w2 < 16; w2++) s += red[w2][t];
        binv[t] = 1.0f / s;
    }
    __syncthreads();

    float* e0 = e_out + ((size_t)b * TD + j0) * TE;
    e0[0 * TE + i] = p0 * binv[0];
    e0[1 * TE + i] = p1 * binv[1];
    e0[2 * TE + i] = p2 * binv[2];
    e0[3 * TE + i] = p3 * binv[3];
}

// ---------------------------------------------------------------------------
// Context GEMM, double-buffered (unchanged from R5 passing version).
// ---------------------------------------------------------------------------
__global__ __launch_bounds__(256) void ctx_gemm(const float* __restrict__ P,
                                                const float* __restrict__ enc,
                                                float* __restrict__ c_out) {
    __shared__ float As[2][16][68];
    __shared__ float Bs[2][16][64];

    int b  = blockIdx.z;
    int j0 = blockIdx.y * 64;
    int h0 = blockIdx.x * 64;
    int t  = threadIdx.x;
    int tx = t & 15;
    int ty = t >> 4;

    ull acc2[2][4];
#pragma unroll
    for (int rp = 0; rp < 2; rp++)
#pragma unroll
        for (int c = 0; c < 4; c++) acc2[rp][c] = 0ull;

    const float* Pb = P   + (size_t)b * TD * TE;
    const float* eb = enc + (size_t)b * TE * H;

    int jj = t >> 2, kq = t & 3;
    int kb = t >> 4, hq = t & 15;

    {
        float4 aReg = *(const float4*)&Pb[(j0 + jj) * TE + kq * 4];
        float4 bReg = *(const float4*)&eb[kb * H + h0 + hq * 4];
        As[0][kq * 4 + 0][jj] = aReg.x;
        As[0][kq * 4 + 1][jj] = aReg.y;
        As[0][kq * 4 + 2][jj] = aReg.z;
        As[0][kq * 4 + 3][jj] = aReg.w;
        *(float4*)&Bs[0][kb][hq * 4] = bReg;
    }
    __syncthreads();

#pragma unroll 1
    for (int kt = 0; kt < 32; kt++) {
        int cur = kt & 1;
        float4 aReg, bReg;
        if (kt < 31) {
            int k0 = (kt + 1) * 16;
            aReg = *(const float4*)&Pb[(j0 + jj) * TE + k0 + kq * 4];
            bReg = *(const float4*)&eb[(k0 + kb) * H + h0 + hq * 4];
        }
#pragma unroll
        for (int kk = 0; kk < 16; kk++) {
            float4 a  = *(float4*)&As[cur][kk][ty * 4];
            float4 bb = *(float4*)&Bs[cur][kk][tx * 4];
            micro_fma2(acc2, a, bb);
        }
        if (kt < 31) {
            int nxt = cur ^ 1;
            As[nxt][kq * 4 + 0][jj] = aReg.x;
            As[nxt][kq * 4 + 1][jj] = aReg.y;
            As[nxt][kq * 4 + 2][jj] = aReg.z;
            As[nxt][kq * 4 + 3][jj] = aReg.w;
            *(float4*)&Bs[nxt][kb][hq * 4] = bReg;
            __syncthreads();
        }
    }

    float o[4][4];
#pragma unroll
    for (int rp = 0; rp < 2; rp++)
#pragma unroll
        for (int c = 0; c < 4; c++)
            upk2(acc2[rp][c], o[2 * rp][c], o[2 * rp + 1][c]);

#pragma unroll
    for (int r = 0; r < 4; r++) {
        float4 v = make_float4(o[r][0], o[r][1], o[r][2], o[r][3]);
        *(float4*)&c_out[((size_t)b * TD + j0 + ty * 4 + r) * H + h0 + tx * 4] = v;
    }
}

// ---------------------------------------------------------------------------
extern "C" void kernel_launch(void* const* d_in, const int* in_sizes, int n_in,
                              void* d_out, int out_size) {
    const float* enc = (const float*)d_in[0];  // [B,TE,H]
    const float* dec = (const float*)d_in[1];  // [B,TD,H]
    const float* W   = (const float*)d_in[2];  // [H,H]
    const float* U   = (const float*)d_in[3];  // [H,H]
    const float* V   = (const float*)d_in[4];  // [H,1]

    float* c_out = (float*)d_out;              // [B,TD,H]
    float* e_out = (float*)d_out + B * TD * H; // [B,TD,TE]

    dim3 gg(12, 4, B);
    gemm_fused<<<gg, 256>>>(enc, dec, W, U);
    energy_kernel<<<B * (TD / 4), 512>>>(V, e_out);
    dim3 gc(H / 64, TD / 64, B);
    ctx_gemm<<<gc, 256>>>(e_out, enc, c_out);
}

// round 9
// speedup vs baseline: 1.0171x; 1.0171x over previous
#include <cuda_runtime.h>
#include <cuda_fp16.h>
#include <cstdint>

#define B 8
#define TE 512
#define TD 256
#define H 256

typedef unsigned long long ull;
typedef unsigned int uint;

// Scratch (device globals: no allocations allowed)
__device__ float g_WeT[B * H * TE];  // [b][h][i]
__device__ float g_Uh [B * TD * H];  // [b][j][h]

// ---- packed fp32x2 helpers ----
__device__ __forceinline__ ull pk2(float lo, float hi) {
    ull r; asm("mov.b64 %0, {%1, %2};" : "=l"(r) : "f"(lo), "f"(hi)); return r;
}
__device__ __forceinline__ ull fma2(ull a, ull b, ull c) {
    ull d; asm("fma.rn.f32x2 %0, %1, %2, %3;" : "=l"(d) : "l"(a), "l"(b), "l"(c)); return d;
}
__device__ __forceinline__ void upk2(ull v, float& lo, float& hi) {
    asm("mov.b64 {%0, %1}, %2;" : "=f"(lo), "=f"(hi) : "l"(v));
}

// half2 tanh via MUFU (2 tanh per MUFU slot)
__device__ __forceinline__ __half2 tanh_h2(__half2 x) {
    uint y, xi = *(uint*)&x;
    asm("tanh.approx.f16x2 %0, %1;" : "=r"(y) : "r"(xi));
    return *(__half2*)&y;
}

// 4x4 micro-tile step, rows packed in pairs, cols duplicated
__device__ __forceinline__ void micro_fma2(ull acc2[2][4], float4 a, float4 bb) {
    ull pa0 = pk2(a.x, a.y);
    ull pa1 = pk2(a.z, a.w);
    ull pb0 = pk2(bb.x, bb.x);
    ull pb1 = pk2(bb.y, bb.y);
    ull pb2 = pk2(bb.z, bb.z);
    ull pb3 = pk2(bb.w, bb.w);
    acc2[0][0] = fma2(pa0, pb0, acc2[0][0]);
    acc2[0][1] = fma2(pa0, pb1, acc2[0][1]);
    acc2[0][2] = fma2(pa0, pb2, acc2[0][2]);
    acc2[0][3] = fma2(pa0, pb3, acc2[0][3]);
    acc2[1][0] = fma2(pa1, pb0, acc2[1][0]);
    acc2[1][1] = fma2(pa1, pb1, acc2[1][1]);
    acc2[1][2] = fma2(pa1, pb2, acc2[1][2]);
    acc2[1][3] = fma2(pa1, pb3, acc2[1][3]);
}

// ---------------------------------------------------------------------------
// Fused GEMM, double-buffered (unchanged from R5/R6 passing version).
// ---------------------------------------------------------------------------
__global__ __launch_bounds__(256) void gemm_fused(const float* __restrict__ enc,
                                                  const float* __restrict__ dec,
                                                  const float* __restrict__ W,
                                                  const float* __restrict__ U) {
    __shared__ float As[2][16][64];
    __shared__ float Bs[2][16][68];

    int b = blockIdx.z;
    int t = threadIdx.x;
    int tx = t & 15;
    int ty = t >> 4;

    ull acc2[2][4];
#pragma unroll
    for (int rp = 0; rp < 2; rp++)
#pragma unroll
        for (int c = 0; c < 4; c++) acc2[rp][c] = 0ull;

    bool weT = (blockIdx.x < 8);
    const float* Wm  = weT ? W : U;
    const float* act = weT ? (enc + (size_t)b * TE * H) : (dec + (size_t)b * TD * H);
    int h0 = blockIdx.y * 64;
    int c0 = weT ? blockIdx.x * 64 : (blockIdx.x - 8) * 64;

    int ka = t >> 4, hq = t & 15;
    int cc = t >> 2, kq = t & 3;

    {
        float4 aReg = *(const float4*)&Wm[ka * H + h0 + hq * 4];
        float4 bReg = *(const float4*)&act[(c0 + cc) * H + kq * 4];
        *(float4*)&As[0][ka][hq * 4] = aReg;
        Bs[0][kq * 4 + 0][cc] = bReg.x;
        Bs[0][kq * 4 + 1][cc] = bReg.y;
        Bs[0][kq * 4 + 2][cc] = bReg.z;
        Bs[0][kq * 4 + 3][cc] = bReg.w;
    }
    __syncthreads();

    if (weT) {
#pragma unroll 1
        for (int kt = 0; kt < 16; kt++) {
            int cur = kt & 1;
            float4 aReg, bReg;
            if (kt < 15) {
                int k0 = (kt + 1) * 16;
                aReg = *(const float4*)&Wm[(k0 + ka) * H + h0 + hq * 4];
                bReg = *(const float4*)&act[(c0 + cc) * H + k0 + kq * 4];
            }
#pragma unroll
            for (int kk = 0; kk < 16; kk++) {
                float4 a  = *(float4*)&As[cur][kk][ty * 4];
                float4 bb = *(float4*)&Bs[cur][kk][tx * 4];
                micro_fma2(acc2, a, bb);
            }
            if (kt < 15) {
                int nxt = cur ^ 1;
                *(float4*)&As[nxt][ka][hq * 4] = aReg;
                Bs[nxt][kq * 4 + 0][cc] = bReg.x;
                Bs[nxt][kq * 4 + 1][cc] = bReg.y;
                Bs[nxt][kq * 4 + 2][cc] = bReg.z;
                Bs[nxt][kq * 4 + 3][cc] = bReg.w;
                __syncthreads();
            }
        }
        float o[4][4];
#pragma unroll
        for (int rp = 0; rp < 2; rp++)
#pragma unroll
            for (int c = 0; c < 4; c++)
                upk2(acc2[rp][c], o[2 * rp][c], o[2 * rp + 1][c]);
        float* out = g_WeT + (size_t)b * H * TE;
#pragma unroll
        for (int r = 0; r < 4; r++) {
            float4 v = make_float4(o[r][0], o[r][1], o[r][2], o[r][3]);
            *(float4*)&out[(h0 + ty * 4 + r) * TE + c0 + tx * 4] = v;
        }
    } else {
#pragma unroll 1
        for (int kt = 0; kt < 16; kt++) {
            int cur = kt & 1;
            float4 aReg, bReg;
            if (kt < 15) {
                int k0 = (kt + 1) * 16;
                aReg = *(const float4*)&Wm[(k0 + ka) * H + h0 + hq * 4];
                bReg = *(const float4*)&act[(c0 + cc) * H + k0 + kq * 4];
            }
#pragma unroll
            for (int kk = 0; kk < 16; kk++) {
                float4 a  = *(float4*)&Bs[cur][kk][ty * 4];
                float4 bb = *(float4*)&As[cur][kk][tx * 4];
                micro_fma2(acc2, a, bb);
            }
            if (kt < 15) {
                int nxt = cur ^ 1;
                *(float4*)&As[nxt][ka][hq * 4] = aReg;
                Bs[nxt][kq * 4 + 0][cc] = bReg.x;
                Bs[nxt][kq * 4 + 1][cc] = bReg.y;
                Bs[nxt][kq * 4 + 2][cc] = bReg.z;
                Bs[nxt][kq * 4 + 3][cc] = bReg.w;
                __syncthreads();
            }
        }
        float o[4][4];
#pragma unroll
        for (int rp = 0; rp < 2; rp++)
#pragma unroll
            for (int c = 0; c < 4; c++)
                upk2(acc2[rp][c], o[2 * rp][c], o[2 * rp + 1][c]);
        float* out = g_Uh + (size_t)b * TD * H;
#pragma unroll
        for (int r = 0; r < 4; r++) {
            float4 v = make_float4(o[r][0], o[r][1], o[r][2], o[r][3]);
            *(float4*)&out[(c0 + ty * 4 + r) * H + h0 + tx * 4] = v;
        }
    }
}

// ---------------------------------------------------------------------------
// Energy + softmax. f16x2 MUFU tanh with HALF arithmetic for the add
// (u pre-converted to half2 j-pairs in smem; w dup'd to half2 once per h).
// f32 accumulation. JT=4 -> 512 blocks, 512 threads.
// ---------------------------------------------------------------------------
__global__ __launch_bounds__(512) void energy_kernel(const float* __restrict__ Va,
                                                     float* __restrict__ e_out) {
    __shared__ __half2 Uh2[H * 2];   // [h][pair]: pair0=(j0,j1), pair1=(j2,j3)
    __shared__ float Vs[H];
    __shared__ float red[16][4];
    __shared__ float binv[4];

    int t  = threadIdx.x;
    int b  = blockIdx.x >> 6;            // TD/4 = 64 tiles per batch
    int j0 = (blockIdx.x & 63) * 4;

    if (t < H) {
        int h = t;
        const float* ub = g_Uh + ((size_t)b * TD + j0) * H + h;
        float u0 = ub[0 * H];
        float u1 = ub[1 * H];
        float u2 = ub[2 * H];
        float u3 = ub[3 * H];
        Uh2[h * 2 + 0] = __floats2half2_rn(u0, u1);
        Uh2[h * 2 + 1] = __floats2half2_rn(u2, u3);
        Vs[h] = Va[h];
    }
    __syncthreads();

    const int i = t;
    const float* wp = g_WeT + (size_t)b * H * TE + i;

    float acc0 = 0.f, acc1 = 0.f, acc2 = 0.f, acc3 = 0.f;
#pragma unroll 8
    for (int h = 0; h < H; h++) {
        float w = wp[h * TE];
        __half2 wd = __float2half2_rn(w);            // 1 cvt (dup)
        __half2 u01 = Uh2[h * 2 + 0];
        __half2 u23 = Uh2[h * 2 + 1];
        __half2 t01 = tanh_h2(__hadd2(wd, u01));     // 1 HADD2 + 1 MUFU
        __half2 t23 = tanh_h2(__hadd2(wd, u23));
        float2 f01 = __half22float2(t01);            // 2 cvt
        float2 f23 = __half22float2(t23);
        float v = Vs[h];
        acc0 = fmaf(v, f01.x, acc0);
        acc1 = fmaf(v, f01.y, acc1);
        acc2 = fmaf(v, f23.x, acc2);
        acc3 = fmaf(v, f23.y, acc3);
    }

    // ---- softmax over i (no max subtraction; |energy| <= sum|V| <= ~13) ----
    float p0 = __expf(acc0);
    float p1 = __expf(acc1);
    float p2 = __expf(acc2);
    float p3 = __expf(acc3);

    int lane = t & 31, wrp = t >> 5;
    float s0 = p0, s1 = p1, s2 = p2, s3 = p3;
#pragma unroll
    for (int o = 16; o; o >>= 1) {
        s0 += __shfl_xor_sync(0xffffffffu, s0, o);
        s1 += __shfl_xor_sync(0xffffffffu, s1, o);
        s2 += __shfl_xor_sync(0xffffffffu, s2, o);
        s3 += __shfl_xor_sync(0xffffffffu, s3, o);
    }
    if (lane == 0) { red[wrp][0] = s0; red[wrp][1] = s1; red[wrp][2] = s2; red[wrp][3] = s3; }
    __syncthreads();
    if (t < 4) {
        float s = 0.f;
#pragma unroll
        for (int w2 = 0; w2 < 16; w2++) s += red[w2][t];
        binv[t] = 1.0f / s;
    }
    __syncthreads();

    float* e0 = e_out + ((size_t)b * TD + j0) * TE;
    e0[0 * TE + i] = p0 * binv[0];
    e0[1 * TE + i] = p1 * binv[1];
    e0[2 * TE + i] = p2 * binv[2];
    e0[3 * TE + i] = p3 * binv[3];
}

// ---------------------------------------------------------------------------
// Context GEMM, double-buffered (unchanged from R5/R6 passing version).
// ---------------------------------------------------------------------------
__global__ __launch_bounds__(256) void ctx_gemm(const float* __restrict__ P,
                                                const float* __restrict__ enc,
                                                float* __restrict__ c_out) {
    __shared__ float As[2][16][68];
    __shared__ float Bs[2][16][64];

    int b  = blockIdx.z;
    int j0 = blockIdx.y * 64;
    int h0 = blockIdx.x * 64;
    int t  = threadIdx.x;
    int tx = t & 15;
    int ty = t >> 4;

    ull acc2[2][4];
#pragma unroll
    for (int rp = 0; rp < 2; rp++)
#pragma unroll
        for (int c = 0; c < 4; c++) acc2[rp][c] = 0ull;

    const float* Pb = P   + (size_t)b * TD * TE;
    const float* eb = enc + (size_t)b * TE * H;

    int jj = t >> 2, kq = t & 3;
    int kb = t >> 4, hq = t & 15;

    {
        float4 aReg = *(const float4*)&Pb[(j0 + jj) * TE + kq * 4];
        float4 bReg = *(const float4*)&eb[kb * H + h0 + hq * 4];
        As[0][kq * 4 + 0][jj] = aReg.x;
        As[0][kq * 4 + 1][jj] = aReg.y;
        As[0][kq * 4 + 2][jj] = aReg.z;
        As[0][kq * 4 + 3][jj] = aReg.w;
        *(float4*)&Bs[0][kb][hq * 4] = bReg;
    }
    __syncthreads();

#pragma unroll 1
    for (int kt = 0; kt < 32; kt++) {
        int cur = kt & 1;
        float4 aReg, bReg;
        if (kt < 31) {
            int k0 = (kt + 1) * 16;
            aReg = *(const float4*)&Pb[(j0 + jj) * TE + k0 + kq * 4];
            bReg = *(const float4*)&eb[(k0 + kb) * H + h0 + hq * 4];
        }
#pragma unroll
        for (int kk = 0; kk < 16; kk++) {
            float4 a  = *(float4*)&As[cur][kk][ty * 4];
            float4 bb = *(float4*)&Bs[cur][kk][tx * 4];
            micro_fma2(acc2, a, bb);
        }
        if (kt < 31) {
            int nxt = cur ^ 1;
            As[nxt][kq * 4 + 0][jj] = aReg.x;
            As[nxt][kq * 4 + 1][jj] = aReg.y;
            As[nxt][kq * 4 + 2][jj] = aReg.z;
            As[nxt][kq * 4 + 3][jj] = aReg.w;
            *(float4*)&Bs[nxt][kb][hq * 4] = bReg;
            __syncthreads();
        }
    }

    float o[4][4];
#pragma unroll
    for (int rp = 0; rp < 2; rp++)
#pragma unroll
        for (int c = 0; c < 4; c++)
            upk2(acc2[rp][c], o[2 * rp][c], o[2 * rp + 1][c]);

#pragma unroll
    for (int r = 0; r < 4; r++) {
        float4 v = make_float4(o[r][0], o[r][1], o[r][2], o[r][3]);
        *(float4*)&c_out[((size_t)b * TD + j0 + ty * 4 + r) * H + h0 + tx * 4] = v;
    }
}

// ---------------------------------------------------------------------------
extern "C" void kernel_launch(void* const* d_in, const int* in_sizes, int n_in,
                              void* d_out, int out_size) {
    const float* enc = (const float*)d_in[0];  // [B,TE,H]
    const float* dec = (const float*)d_in[1];  // [B,TD,H]
    const float* W   = (const float*)d_in[2];  // [H,H]
    const float* U   = (const float*)d_in[3];  // [H,H]
    const float* V   = (const float*)d_in[4];  // [H,1]

    float* c_out = (float*)d_out;              // [B,TD,H]
    float* e_out = (float*)d_out + B * TD * H; // [B,TD,TE]

    dim3 gg(12, 4, B);
    gemm_fused<<<gg, 256>>>(enc, dec, W, U);
    energy_kernel<<<B * (TD / 4), 512>>>(V, e_out);
    dim3 gc(H / 64, TD / 64, B);
    ctx_gemm<<<gc, 256>>>(e_out, enc, c_out);
}